// round 14
// baseline (speedup 1.0000x reference)
#include <cuda_runtime.h>
#include <cuda_bf16.h>
#include <cstdint>

// MaxBlurPooling1D: x (16, 8192, 256) f32 -> z (16, 4096, 256) f32
// z[b,j,c] = w0*m[2j-1] + w1*m[2j] + w2*m[2j+1] + w3*m[2j+2]
//   m[l] = max(x[l], x[l+1]) for l<=L-2 ; m[L-1] = x[L-1] ; m[-1] = m[L] = 0
//
// Round-13 (on top of R12's TMA win: 26.7us, DRAM 77.3%):
//  - JPT 16 -> 32 per block; tile = 67 contiguous rows (68.6KB)
//  - tile loaded as TWO cp.async.bulk stages (35 rows + <=32 rows), both
//    issued back-to-back at block start on separate mbarriers; compute of
//    outputs 0..15 overlaps stage-2's transfer -> stage-2 latency hidden
//  - read amplification 1.094x -> 1.047x (-4.5% issue traffic)
//  - smem 69KB -> 3 blocks/SM (needs MaxDynamicSharedMemorySize attr)

#define L_DIM  8192
#define CF     256                 // f32 channels per row
#define C4     64                  // float4 lanes per row
#define J_OUT  4096
#define JPT    32                  // output rows per block
#define ROWB   1024                // bytes per input row
#define S1_ROWS 35                 // stage-1 rows (fixed)
#define TILE_ROWS 67               // max total rows per chunk footprint
#define SMEM_BYTES (256 + TILE_ROWS * ROWB)

__device__ __forceinline__ float4 f4max(float4 a, float4 b) {
    return make_float4(fmaxf(a.x, b.x), fmaxf(a.y, b.y),
                       fmaxf(a.z, b.z), fmaxf(a.w, b.w));
}

__device__ __forceinline__ void mbar_wait0(uint32_t mbar_u32) {
    uint32_t ready = 0;
    while (!ready) {
        asm volatile(
            "{\n\t.reg .pred p;\n\t"
            "mbarrier.try_wait.parity.acquire.cta.shared::cta.b64 p, [%1], 0, 0x989680;\n\t"
            "selp.b32 %0, 1, 0, p;\n\t}"
            : "=r"(ready) : "r"(mbar_u32) : "memory");
    }
}

__global__ void __launch_bounds__(128)
mbp1d_tma_kernel(const float* __restrict__ x,
                 const float* __restrict__ blur,
                 const float* __restrict__ avg,
                 float4*      __restrict__ z)
{
    extern __shared__ __align__(128) char smem[];
    uint64_t* mbar0 = (uint64_t*)smem;                // [0:8)
    uint64_t* mbar1 = (uint64_t*)(smem + 8);          // [8:16)
    float4*   tile  = (float4*)(smem + 256);          // 67 rows x 1KB

    const int c   = threadIdx.x;                      // 0..63 float4 lane
    const int ty  = threadIdx.y;                      // 0..1
    const int tid = ty * 64 + c;
    const int b   = blockIdx.y;                       // batch
    const int j0  = blockIdx.x * JPT;                 // first output row of chunk

    // Input footprint: rows [start, end) of batch b; split at start+35.
    const int start = (j0 == 0) ? 0 : (2 * j0 - 1);
    const int end   = min(L_DIM, 2 * j0 + 66);
    const int s2r   = start + S1_ROWS;                // stage-2 first row
    const int n1    = S1_ROWS * ROWB;
    const int n2    = (end - s2r) * ROWB;             // 30..32 rows

    const uint32_t mb0 = (uint32_t)__cvta_generic_to_shared(mbar0);
    const uint32_t mb1 = (uint32_t)__cvta_generic_to_shared(mbar1);
    const uint32_t t0  = (uint32_t)__cvta_generic_to_shared(tile);
    const uint32_t t1  = t0 + (uint32_t)n1;

    if (tid == 0) {
        asm volatile("mbarrier.init.shared.b64 [%0], 1;" :: "r"(mb0));
        asm volatile("mbarrier.init.shared.b64 [%0], 1;" :: "r"(mb1));
    }
    __syncthreads();

    if (tid == 0) {
        const char* src = (const char*)(x + (size_t)b * L_DIM * CF);
        // Stage 1: rows [start, start+35)
        asm volatile("mbarrier.arrive.expect_tx.shared.b64 _, [%0], %1;"
                     :: "r"(mb0), "r"((uint32_t)n1) : "memory");
        asm volatile("cp.async.bulk.shared::cta.global.mbarrier::complete_tx::bytes "
                     "[%0], [%1], %2, [%3];"
                     :: "r"(t0), "l"(src + (size_t)start * ROWB),
                        "r"((uint32_t)n1), "r"(mb0) : "memory");
        // Stage 2: rows [start+35, end) — issued immediately, waited later
        asm volatile("mbarrier.arrive.expect_tx.shared.b64 _, [%0], %1;"
                     :: "r"(mb1), "r"((uint32_t)n2) : "memory");
        asm volatile("cp.async.bulk.shared::cta.global.mbarrier::complete_tx::bytes "
                     "[%0], [%1], %2, [%3];"
                     :: "r"(t1), "l"(src + (size_t)s2r * ROWB),
                        "r"((uint32_t)n2), "r"(mb1) : "memory");
    }

    // Weights: fold blur (3-tap) and avg (2-tap) into 4 taps over m[].
    const float b0 = blur[0], b1 = blur[1], b2 = blur[2];
    const float a0 = avg[0],  a1 = avg[1];
    const float w0 = a0 * b0;
    const float w1 = a0 * b1 + a1 * b0;
    const float w2 = a0 * b2 + a1 * b1;
    const float w3 = a1 * b2;

    const float4* S    = tile + c;                    // row stride C4
    const float4  zero = make_float4(0.f, 0.f, 0.f, 0.f);

    // ---- Stage 1 compute: outputs j0 + [0,16), from rows start..start+34 ----
    mbar_wait0(mb0);
    {
        const int js = j0 + 8 * ty;
        float4* zb = z + ((size_t)b * J_OUT + js) * C4 + c;

        float4 mA, mB, xlast;
        {
            const float4 x0 = S[(2 * js - start) * C4];
            const float4 x1 = S[(2 * js + 1 - start) * C4];
            mA = (js == 0) ? zero : f4max(S[(2 * js - 1 - start) * C4], x0);
            mB = f4max(x0, x1);
            xlast = x1;
        }

        #pragma unroll
        for (int t = 0; t < 8; ++t) {
            const int r2 = 2 * (js + t) + 2;          // <= 2*j0+32 <= start+33: in stage 1
            const float4 x2 = S[(r2 - start) * C4];
            const float4 x3 = S[(r2 + 1 - start) * C4];
            const float4 mC = f4max(xlast, x2);       // m[2j+1]
            const float4 mD = f4max(x2, x3);          // m[2j+2]
            xlast = x3;

            float4 o;
            o.x = w0 * mA.x + w1 * mB.x + w2 * mC.x + w3 * mD.x;
            o.y = w0 * mA.y + w1 * mB.y + w2 * mC.y + w3 * mD.y;
            o.z = w0 * mA.z + w1 * mB.z + w2 * mC.z + w3 * mD.z;
            o.w = w0 * mA.w + w1 * mB.w + w2 * mC.w + w3 * mD.w;
            zb[(size_t)t * C4] = o;

            mA = mC;
            mB = mD;
        }
    }

    // ---- Stage 2 compute: outputs j0 + [16,32), rows up to end-1 ----
    mbar_wait0(mb1);
    {
        const int js = j0 + 16 + 8 * ty;
        float4* zb = z + ((size_t)b * J_OUT + js) * C4 + c;

        float4 mA, mB, xlast;
        {
            // rows 2js-1 .. 2js+1 >= 2j0+31 = start+32: present (stage 1/2)
            const float4 x0 = S[(2 * js - start) * C4];
            const float4 x1 = S[(2 * js + 1 - start) * C4];
            mA = f4max(S[(2 * js - 1 - start) * C4], x0);
            mB = f4max(x0, x1);
            xlast = x1;
        }

        #pragma unroll
        for (int t = 0; t < 8; ++t) {
            const int j  = js + t;
            const int r2 = 2 * j + 2;
            float4 mC, mD;
            if (r2 < L_DIM) {
                const float4 x2 = S[(r2 - start) * C4];
                const float4 x3 = S[(r2 + 1 - start) * C4];
                mC = f4max(xlast, x2);                // m[2j+1]
                mD = f4max(x2, x3);                   // m[2j+2]
                xlast = x3;
            } else {
                // j = 4095: m[8191] = x[8191] (NEG_INF pad), m[8192] = 0
                mC = xlast;
                mD = zero;
            }

            float4 o;
            o.x = w0 * mA.x + w1 * mB.x + w2 * mC.x + w3 * mD.x;
            o.y = w0 * mA.y + w1 * mB.y + w2 * mC.y + w3 * mD.y;
            o.z = w0 * mA.z + w1 * mB.z + w2 * mC.z + w3 * mD.z;
            o.w = w0 * mA.w + w1 * mB.w + w2 * mC.w + w3 * mD.w;
            zb[(size_t)t * C4] = o;

            mA = mC;
            mB = mD;
        }
    }
}

extern "C" void kernel_launch(void* const* d_in, const int* in_sizes, int n_in,
                              void* d_out, int out_size)
{
    const float* x    = (const float*)d_in[0];     // (16, 8192, 256) f32
    const float* blur = (const float*)d_in[1];     // (3,1,1)
    const float* avg  = (const float*)d_in[2];     // (2,1,1)
    float4*      z    = (float4*)d_out;            // (16, 4096, 256) f32

    (void)in_sizes; (void)n_in; (void)out_size;

    // >48KB dynamic smem requires opt-in (host-side attr; capture-safe,
    // idempotent — called every launch).
    cudaFuncSetAttribute(mbp1d_tma_kernel,
                         cudaFuncAttributeMaxDynamicSharedMemorySize, SMEM_BYTES);

    dim3 block(C4, 2);                             // (64, 2) = 128 threads
    dim3 grid(J_OUT / JPT, 16);                    // (128, 16) = 2048 blocks
    mbp1d_tma_kernel<<<grid, block, SMEM_BYTES>>>(x, blur, avg, z);
}